// round 1
// baseline (speedup 1.0000x reference)
#include <cuda_runtime.h>
#include <cstdint>

#define B_TOTAL 8192
#define T_STEPS 28
#define I_DIM 28
#define H_DIM 128
#define C_DIM 10

// 117MB scratch for precomputed layer-0 input GEMM (+ both layer-0 biases folded in).
// __device__ global array: the sanctioned no-cudaMalloc scratch mechanism.
__device__ float g_xw0[(size_t)B_TOTAL * T_STEPS * H_DIM];

// ---------------- packed fp32x2 helpers (Blackwell FFMA2 path) ----------------
__device__ __forceinline__ unsigned long long ffma2(unsigned long long a,
                                                    unsigned long long b,
                                                    unsigned long long c) {
    unsigned long long d;
    asm("fma.rn.f32x2 %0, %1, %2, %3;" : "=l"(d) : "l"(a), "l"(b), "l"(c));
    return d;
}
__device__ __forceinline__ unsigned long long dup32(float x) {
    unsigned long long d;
    asm("mov.b64 %0, {%1, %1};" : "=l"(d) : "f"(x));
    return d;
}
__device__ __forceinline__ unsigned long long pack2(float lo, float hi) {
    unsigned long long d;
    asm("mov.b64 %0, {%1, %2};" : "=l"(d) : "f"(lo), "f"(hi));
    return d;
}
__device__ __forceinline__ void unpack2(unsigned long long v, float& lo, float& hi) {
    asm("mov.b64 {%0, %1}, %2;" : "=f"(lo), "=f"(hi) : "l"(v));
}

// tanh via exp: 1 - 2/(e^{2x}+1). 2 MUFU ops, rel err ~1e-6.
// x->+inf: e=inf -> 1-0 = 1.  x->-inf: e=0 -> 1-2 = -1.  Correct saturation.
__device__ __forceinline__ float fast_tanh(float x) {
    float e = __expf(2.0f * x);
    return 1.0f - __fdividef(2.0f, e + 1.0f);
}

// h-buffer swizzle: rows are 32 bytes (8 samples * 4B) at k*32. Writes are
// per-unit rows (lane stride 128B -> would be 32-way conflicted); XOR bits[5:6]
// with (k>>2)&3 so each group of 4 lanes fills one 128B phase conflict-free.
// Reads are warp-broadcast, so swizzle is harmless there.
__device__ __forceinline__ int hswz(int k) {
    return (k * 32) ^ (((k >> 2) & 3) << 5);
}

// ---------------- kernel 1: xw0[b][t][j] = b_ih0[j]+b_hh0[j] + sum_d x[b][t][d]*W_ih0[j][d]
__global__ void __launch_bounds__(128) xw0_kernel(const float* __restrict__ x,
                                                  const float* __restrict__ W_ih0,
                                                  const float* __restrict__ b_ih0,
                                                  const float* __restrict__ b_hh0) {
    __shared__ float xs[T_STEPS * I_DIM];  // 784 floats
    const int b = blockIdx.x;
    const int j = threadIdx.x;  // hidden unit 0..127
    const float* xb = x + (size_t)b * T_STEPS * I_DIM;
    for (int i = j; i < T_STEPS * I_DIM; i += 128) xs[i] = xb[i];
    float w[I_DIM];
#pragma unroll
    for (int d = 0; d < I_DIM; d++) w[d] = W_ih0[j * I_DIM + d];
    const float bias = b_ih0[j] + b_hh0[j];
    __syncthreads();
    float* outb = g_xw0 + (size_t)b * T_STEPS * H_DIM;
#pragma unroll 4
    for (int t = 0; t < T_STEPS; t++) {
        float acc = bias;
#pragma unroll
        for (int d = 0; d < I_DIM; d++) acc = fmaf(w[d], xs[t * I_DIM + d], acc);
        outb[t * H_DIM + j] = acc;
    }
}

// ---------------- kernel 2: fused 2-layer recurrence + FC ----------------
// SMEM layout (dynamic, 229376 B total):
//   [0      , 65536 )  W_hh0^T  (Wt[k][j], j contiguous)
//   [65536  , 131072)  W_ih1^T
//   [131072 , 196608)  W_hh1^T
//   [196608 , 212992)  h0 buffers: 4 warps x 4KB (128 rows x 32B, swizzled)
//   [212992 , 229376)  h1 buffers: 4 warps x 4KB
__global__ void __launch_bounds__(128, 1) rnn_fused_kernel(
    const float* __restrict__ W_hh0, const float* __restrict__ W_ih1,
    const float* __restrict__ W_hh1, const float* __restrict__ b_ih1,
    const float* __restrict__ b_hh1, const float* __restrict__ fc_w,
    const float* __restrict__ fc_b, float* __restrict__ out) {
    extern __shared__ char smem[];
    float* w0  = (float*)(smem);
    float* wi1 = (float*)(smem + 65536);
    float* wh1 = (float*)(smem + 131072);
    const int tid = threadIdx.x;

    // Load + transpose the three 128x128 weight matrices into SMEM.
    // Thread j reads row j (contiguous float4s), scatters to Wt[k][j]
    // (lane-contiguous STS -> conflict-free).
    {
        const int j = tid;
#pragma unroll 1
        for (int m = 0; m < 3; m++) {
            const float* S = (m == 0 ? W_hh0 : (m == 1 ? W_ih1 : W_hh1)) + j * H_DIM;
            float* D = (m == 0 ? w0 : (m == 1 ? wi1 : wh1));
#pragma unroll 8
            for (int k0 = 0; k0 < H_DIM; k0 += 4) {
                float4 v = *(const float4*)(S + k0);
                D[(k0 + 0) * H_DIM + j] = v.x;
                D[(k0 + 1) * H_DIM + j] = v.y;
                D[(k0 + 2) * H_DIM + j] = v.z;
                D[(k0 + 3) * H_DIM + j] = v.w;
            }
        }
    }
    // Zero all h buffers (32KB).
    for (int i = tid; i < 2048; i += 128)
        ((float4*)(smem + 196608))[i] = make_float4(0.f, 0.f, 0.f, 0.f);
    __syncthreads();

    const int g = tid >> 5;   // warp id: owns 8 samples, self-contained recurrence
    const int L = tid & 31;   // lane: owns hidden units u0..u0+3
    const int u0 = L * 4;
    char* h0b = smem + 196608 + g * 4096;
    char* h1b = smem + 212992 + g * 4096;
    const int sbase = blockIdx.x * 32 + g * 8;

    unsigned long long bias1d[4];
#pragma unroll
    for (int i = 0; i < 4; i++) bias1d[i] = dup32(b_ih1[u0 + i] + b_hh1[u0 + i]);

    // Prefetch xw0 for t=0: float4 per sample (units u0..u0+3).
    const float* xw_base = g_xw0 + (size_t)sbase * T_STEPS * H_DIM + u0;
    float4 pf[8];
#pragma unroll
    for (int s = 0; s < 8; s++)
        pf[s] = *(const float4*)(xw_base + (size_t)s * T_STEPS * H_DIM);

#pragma unroll 1
    for (int t = 0; t < T_STEPS; t++) {
        // ---- layer 0: acc0[unit i][sample-pair sp] init from prefetched xw0
        unsigned long long acc0[4][4];
#pragma unroll
        for (int sp = 0; sp < 4; sp++) {
            float4 a = pf[2 * sp], b = pf[2 * sp + 1];
            acc0[0][sp] = pack2(a.x, b.x);
            acc0[1][sp] = pack2(a.y, b.y);
            acc0[2][sp] = pack2(a.z, b.z);
            acc0[3][sp] = pack2(a.w, b.w);
        }
        if (t + 1 < T_STEPS) {
#pragma unroll
            for (int s = 0; s < 8; s++)
                pf[s] = *(const float4*)(xw_base + (size_t)s * T_STEPS * H_DIM +
                                         (t + 1) * H_DIM);
        }
        // ---- layer 0 recurrent matvec: acc0 += W_hh0^T[k] * h0[k]
#pragma unroll 4
        for (int k = 0; k < H_DIM; k++) {
            float4 w4 = *(const float4*)(w0 + k * H_DIM + u0);
            unsigned long long wd0 = dup32(w4.x), wd1 = dup32(w4.y);
            unsigned long long wd2 = dup32(w4.z), wd3 = dup32(w4.w);
            const int ro = hswz(k);
#pragma unroll
            for (int sp = 0; sp < 4; sp++) {
                unsigned long long hp = *(const unsigned long long*)(h0b + ro + sp * 8);
                acc0[0][sp] = ffma2(wd0, hp, acc0[0][sp]);
                acc0[1][sp] = ffma2(wd1, hp, acc0[1][sp]);
                acc0[2][sp] = ffma2(wd2, hp, acc0[2][sp]);
                acc0[3][sp] = ffma2(wd3, hp, acc0[3][sp]);
            }
        }
        // tanh, write new h0 (in place; warp-local buffer)
        float hv[4][8];
#pragma unroll
        for (int i = 0; i < 4; i++)
#pragma unroll
            for (int sp = 0; sp < 4; sp++)
                unpack2(acc0[i][sp], hv[i][2 * sp], hv[i][2 * sp + 1]);
#pragma unroll
        for (int i = 0; i < 4; i++)
#pragma unroll
            for (int s = 0; s < 8; s++) hv[i][s] = fast_tanh(hv[i][s]);
        __syncwarp();
#pragma unroll
        for (int i = 0; i < 4; i++) {
            const int ro = hswz(u0 + i);
            *(float4*)(h0b + ro)      = make_float4(hv[i][0], hv[i][1], hv[i][2], hv[i][3]);
            *(float4*)(h0b + ro + 16) = make_float4(hv[i][4], hv[i][5], hv[i][6], hv[i][7]);
        }
        __syncwarp();

        // ---- layer 1: acc1 = bias1 + W_ih1^T*h0_new + W_hh1^T*h1_old
        unsigned long long acc1[4][4];
#pragma unroll
        for (int i = 0; i < 4; i++)
#pragma unroll
            for (int sp = 0; sp < 4; sp++) acc1[i][sp] = bias1d[i];
#pragma unroll 2
        for (int k = 0; k < H_DIM; k++) {
            float4 wa = *(const float4*)(wi1 + k * H_DIM + u0);
            float4 wb = *(const float4*)(wh1 + k * H_DIM + u0);
            unsigned long long wa0 = dup32(wa.x), wa1 = dup32(wa.y);
            unsigned long long wa2 = dup32(wa.z), wa3 = dup32(wa.w);
            unsigned long long wb0 = dup32(wb.x), wb1 = dup32(wb.y);
            unsigned long long wb2 = dup32(wb.z), wb3 = dup32(wb.w);
            const int ro = hswz(k);
#pragma unroll
            for (int sp = 0; sp < 4; sp++) {
                unsigned long long hp0 = *(const unsigned long long*)(h0b + ro + sp * 8);
                unsigned long long hp1 = *(const unsigned long long*)(h1b + ro + sp * 8);
                acc1[0][sp] = ffma2(wa0, hp0, acc1[0][sp]);
                acc1[1][sp] = ffma2(wa1, hp0, acc1[1][sp]);
                acc1[2][sp] = ffma2(wa2, hp0, acc1[2][sp]);
                acc1[3][sp] = ffma2(wa3, hp0, acc1[3][sp]);
                acc1[0][sp] = ffma2(wb0, hp1, acc1[0][sp]);
                acc1[1][sp] = ffma2(wb1, hp1, acc1[1][sp]);
                acc1[2][sp] = ffma2(wb2, hp1, acc1[2][sp]);
                acc1[3][sp] = ffma2(wb3, hp1, acc1[3][sp]);
            }
        }
#pragma unroll
        for (int i = 0; i < 4; i++)
#pragma unroll
            for (int sp = 0; sp < 4; sp++)
                unpack2(acc1[i][sp], hv[i][2 * sp], hv[i][2 * sp + 1]);
#pragma unroll
        for (int i = 0; i < 4; i++)
#pragma unroll
            for (int s = 0; s < 8; s++) hv[i][s] = fast_tanh(hv[i][s]);
        __syncwarp();
#pragma unroll
        for (int i = 0; i < 4; i++) {
            const int ro = hswz(u0 + i);
            *(float4*)(h1b + ro)      = make_float4(hv[i][0], hv[i][1], hv[i][2], hv[i][3]);
            *(float4*)(h1b + ro + 16) = make_float4(hv[i][4], hv[i][5], hv[i][6], hv[i][7]);
        }
        __syncwarp();
    }

    // ---- FC epilogue: out[b][c] = h1_final . fc_w[c] + fc_b[c]
    // 8 samples x 10 classes = 80 items per warp.
    for (int item = L; item < 8 * C_DIM; item += 32) {
        const int s = item / C_DIM;
        const int c = item % C_DIM;
        float acc = fc_b[c];
        const float* fw = fc_w + c * H_DIM;
#pragma unroll 8
        for (int k = 0; k < H_DIM; k++) {
            float hk = *(const float*)(h1b + hswz(k) + s * 4);
            acc = fmaf(hk, fw[k], acc);
        }
        out[(size_t)(sbase + s) * C_DIM + c] = acc;
    }
}

// ---------------- launch ----------------
extern "C" void kernel_launch(void* const* d_in, const int* in_sizes, int n_in,
                              void* d_out, int out_size) {
    (void)in_sizes; (void)n_in; (void)out_size;
    const float* x     = (const float*)d_in[0];
    const float* W_ih0 = (const float*)d_in[1];
    const float* W_hh0 = (const float*)d_in[2];
    const float* b_ih0 = (const float*)d_in[3];
    const float* b_hh0 = (const float*)d_in[4];
    const float* W_ih1 = (const float*)d_in[5];
    const float* W_hh1 = (const float*)d_in[6];
    const float* b_ih1 = (const float*)d_in[7];
    const float* b_hh1 = (const float*)d_in[8];
    const float* fc_w  = (const float*)d_in[9];
    const float* fc_b  = (const float*)d_in[10];
    float* out = (float*)d_out;

    xw0_kernel<<<B_TOTAL, 128>>>(x, W_ih0, b_ih0, b_hh0);

    cudaFuncSetAttribute(rnn_fused_kernel,
                         cudaFuncAttributeMaxDynamicSharedMemorySize, 229376);
    rnn_fused_kernel<<<B_TOTAL / 32, 128, 229376>>>(W_hh0, W_ih1, W_hh1, b_ih1,
                                                    b_hh1, fc_w, fc_b, out);
}

// round 3
// speedup vs baseline: 1.0006x; 1.0006x over previous
#include <cuda_runtime.h>
#include <cstdint>

#define B_TOTAL 8192
#define T_STEPS 28
#define I_DIM 28
#define H_DIM 128
#define C_DIM 10

// 117MB scratch for precomputed layer-0 input GEMM (+ both layer-0 biases folded in).
// __device__ global array: the sanctioned no-cudaMalloc scratch mechanism.
__device__ float g_xw0[(size_t)B_TOTAL * T_STEPS * H_DIM];

// ---------------- packed fp32x2 helpers (Blackwell FFMA2 path) ----------------
__device__ __forceinline__ unsigned long long ffma2(unsigned long long a,
                                                    unsigned long long b,
                                                    unsigned long long c) {
    unsigned long long d;
    asm("fma.rn.f32x2 %0, %1, %2, %3;" : "=l"(d) : "l"(a), "l"(b), "l"(c));
    return d;
}
__device__ __forceinline__ unsigned long long dup32(float x) {
    unsigned long long d;
    asm("mov.b64 %0, {%1, %1};" : "=l"(d) : "f"(x));
    return d;
}
__device__ __forceinline__ unsigned long long pack2(float lo, float hi) {
    unsigned long long d;
    asm("mov.b64 %0, {%1, %2};" : "=l"(d) : "f"(lo), "f"(hi));
    return d;
}
__device__ __forceinline__ void unpack2(unsigned long long v, float& lo, float& hi) {
    asm("mov.b64 {%0, %1}, %2;" : "=f"(lo), "=f"(hi) : "l"(v));
}

// tanh via exp: 1 - 2/(e^{2x}+1). 2 MUFU ops, rel err ~1e-6.
// x->+inf: e=inf -> 1-0 = 1.  x->-inf: e=0 -> 1-2 = -1.  Correct saturation.
__device__ __forceinline__ float fast_tanh(float x) {
    float e = __expf(2.0f * x);
    return 1.0f - __fdividef(2.0f, e + 1.0f);
}

// h-buffer swizzle: rows are 32 bytes (8 samples * 4B) at k*32. Writes are
// per-unit rows (lane stride 128B -> would be 32-way conflicted); XOR bits[5:6]
// with (k>>2)&3 so each group of 4 lanes fills one 128B phase conflict-free.
// Reads are warp-broadcast, so swizzle is harmless there.
__device__ __forceinline__ int hswz(int k) {
    return (k * 32) ^ (((k >> 2) & 3) << 5);
}

// ---------------- kernel 1: xw0[b][t][j] = b_ih0[j]+b_hh0[j] + sum_d x[b][t][d]*W_ih0[j][d]
__global__ void __launch_bounds__(128) xw0_kernel(const float* __restrict__ x,
                                                  const float* __restrict__ W_ih0,
                                                  const float* __restrict__ b_ih0,
                                                  const float* __restrict__ b_hh0) {
    __shared__ float xs[T_STEPS * I_DIM];  // 784 floats
    const int b = blockIdx.x;
    const int j = threadIdx.x;  // hidden unit 0..127
    const float* xb = x + (size_t)b * T_STEPS * I_DIM;
    for (int i = j; i < T_STEPS * I_DIM; i += 128) xs[i] = xb[i];
    float w[I_DIM];
#pragma unroll
    for (int d = 0; d < I_DIM; d++) w[d] = W_ih0[j * I_DIM + d];
    const float bias = b_ih0[j] + b_hh0[j];
    __syncthreads();
    float* outb = g_xw0 + (size_t)b * T_STEPS * H_DIM;
#pragma unroll 4
    for (int t = 0; t < T_STEPS; t++) {
        float acc = bias;
#pragma unroll
        for (int d = 0; d < I_DIM; d++) acc = fmaf(w[d], xs[t * I_DIM + d], acc);
        outb[t * H_DIM + j] = acc;
    }
}

// ---------------- kernel 2: fused 2-layer recurrence + FC ----------------
// SMEM layout (dynamic, 229376 B total):
//   [0      , 65536 )  W_hh0^T  (Wt[k][j], j contiguous)
//   [65536  , 131072)  W_ih1^T
//   [131072 , 196608)  W_hh1^T
//   [196608 , 212992)  h0 buffers: 4 warps x 4KB (128 rows x 32B, swizzled)
//   [212992 , 229376)  h1 buffers: 4 warps x 4KB
__global__ void __launch_bounds__(128, 1) rnn_fused_kernel(
    const float* __restrict__ W_hh0, const float* __restrict__ W_ih1,
    const float* __restrict__ W_hh1, const float* __restrict__ b_ih1,
    const float* __restrict__ b_hh1, const float* __restrict__ fc_w,
    const float* __restrict__ fc_b, float* __restrict__ out) {
    extern __shared__ char smem[];
    float* w0  = (float*)(smem);
    float* wi1 = (float*)(smem + 65536);
    float* wh1 = (float*)(smem + 131072);
    const int tid = threadIdx.x;

    // Load + transpose the three 128x128 weight matrices into SMEM.
    // Thread j reads row j (contiguous float4s), scatters to Wt[k][j]
    // (lane-contiguous STS -> conflict-free).
    {
        const int j = tid;
#pragma unroll 1
        for (int m = 0; m < 3; m++) {
            const float* S = (m == 0 ? W_hh0 : (m == 1 ? W_ih1 : W_hh1)) + j * H_DIM;
            float* D = (m == 0 ? w0 : (m == 1 ? wi1 : wh1));
#pragma unroll 8
            for (int k0 = 0; k0 < H_DIM; k0 += 4) {
                float4 v = *(const float4*)(S + k0);
                D[(k0 + 0) * H_DIM + j] = v.x;
                D[(k0 + 1) * H_DIM + j] = v.y;
                D[(k0 + 2) * H_DIM + j] = v.z;
                D[(k0 + 3) * H_DIM + j] = v.w;
            }
        }
    }
    // Zero all h buffers (32KB).
    for (int i = tid; i < 2048; i += 128)
        ((float4*)(smem + 196608))[i] = make_float4(0.f, 0.f, 0.f, 0.f);
    __syncthreads();

    const int g = tid >> 5;   // warp id: owns 8 samples, self-contained recurrence
    const int L = tid & 31;   // lane: owns hidden units u0..u0+3
    const int u0 = L * 4;
    char* h0b = smem + 196608 + g * 4096;
    char* h1b = smem + 212992 + g * 4096;
    const int sbase = blockIdx.x * 32 + g * 8;

    unsigned long long bias1d[4];
#pragma unroll
    for (int i = 0; i < 4; i++) bias1d[i] = dup32(b_ih1[u0 + i] + b_hh1[u0 + i]);

    // Prefetch xw0 for t=0: float4 per sample (units u0..u0+3).
    const float* xw_base = g_xw0 + (size_t)sbase * T_STEPS * H_DIM + u0;
    float4 pf[8];
#pragma unroll
    for (int s = 0; s < 8; s++)
        pf[s] = *(const float4*)(xw_base + (size_t)s * T_STEPS * H_DIM);

#pragma unroll 1
    for (int t = 0; t < T_STEPS; t++) {
        // ---- layer 0: acc0[unit i][sample-pair sp] init from prefetched xw0
        unsigned long long acc0[4][4];
#pragma unroll
        for (int sp = 0; sp < 4; sp++) {
            float4 a = pf[2 * sp], b = pf[2 * sp + 1];
            acc0[0][sp] = pack2(a.x, b.x);
            acc0[1][sp] = pack2(a.y, b.y);
            acc0[2][sp] = pack2(a.z, b.z);
            acc0[3][sp] = pack2(a.w, b.w);
        }
        if (t + 1 < T_STEPS) {
#pragma unroll
            for (int s = 0; s < 8; s++)
                pf[s] = *(const float4*)(xw_base + (size_t)s * T_STEPS * H_DIM +
                                         (t + 1) * H_DIM);
        }
        // ---- layer 0 recurrent matvec: acc0 += W_hh0^T[k] * h0[k]
#pragma unroll 4
        for (int k = 0; k < H_DIM; k++) {
            float4 w4 = *(const float4*)(w0 + k * H_DIM + u0);
            unsigned long long wd0 = dup32(w4.x), wd1 = dup32(w4.y);
            unsigned long long wd2 = dup32(w4.z), wd3 = dup32(w4.w);
            const int ro = hswz(k);
#pragma unroll
            for (int sp = 0; sp < 4; sp++) {
                unsigned long long hp = *(const unsigned long long*)(h0b + ro + sp * 8);
                acc0[0][sp] = ffma2(wd0, hp, acc0[0][sp]);
                acc0[1][sp] = ffma2(wd1, hp, acc0[1][sp]);
                acc0[2][sp] = ffma2(wd2, hp, acc0[2][sp]);
                acc0[3][sp] = ffma2(wd3, hp, acc0[3][sp]);
            }
        }
        // tanh, write new h0 (in place; warp-local buffer)
        float hv[4][8];
#pragma unroll
        for (int i = 0; i < 4; i++)
#pragma unroll
            for (int sp = 0; sp < 4; sp++)
                unpack2(acc0[i][sp], hv[i][2 * sp], hv[i][2 * sp + 1]);
#pragma unroll
        for (int i = 0; i < 4; i++)
#pragma unroll
            for (int s = 0; s < 8; s++) hv[i][s] = fast_tanh(hv[i][s]);
        __syncwarp();
#pragma unroll
        for (int i = 0; i < 4; i++) {
            const int ro = hswz(u0 + i);
            *(float4*)(h0b + ro)      = make_float4(hv[i][0], hv[i][1], hv[i][2], hv[i][3]);
            *(float4*)(h0b + ro + 16) = make_float4(hv[i][4], hv[i][5], hv[i][6], hv[i][7]);
        }
        __syncwarp();

        // ---- layer 1: acc1 = bias1 + W_ih1^T*h0_new + W_hh1^T*h1_old
        unsigned long long acc1[4][4];
#pragma unroll
        for (int i = 0; i < 4; i++)
#pragma unroll
            for (int sp = 0; sp < 4; sp++) acc1[i][sp] = bias1d[i];
#pragma unroll 2
        for (int k = 0; k < H_DIM; k++) {
            float4 wa = *(const float4*)(wi1 + k * H_DIM + u0);
            float4 wb = *(const float4*)(wh1 + k * H_DIM + u0);
            unsigned long long wa0 = dup32(wa.x), wa1 = dup32(wa.y);
            unsigned long long wa2 = dup32(wa.z), wa3 = dup32(wa.w);
            unsigned long long wb0 = dup32(wb.x), wb1 = dup32(wb.y);
            unsigned long long wb2 = dup32(wb.z), wb3 = dup32(wb.w);
            const int ro = hswz(k);
#pragma unroll
            for (int sp = 0; sp < 4; sp++) {
                unsigned long long hp0 = *(const unsigned long long*)(h0b + ro + sp * 8);
                unsigned long long hp1 = *(const unsigned long long*)(h1b + ro + sp * 8);
                acc1[0][sp] = ffma2(wa0, hp0, acc1[0][sp]);
                acc1[1][sp] = ffma2(wa1, hp0, acc1[1][sp]);
                acc1[2][sp] = ffma2(wa2, hp0, acc1[2][sp]);
                acc1[3][sp] = ffma2(wa3, hp0, acc1[3][sp]);
                acc1[0][sp] = ffma2(wb0, hp1, acc1[0][sp]);
                acc1[1][sp] = ffma2(wb1, hp1, acc1[1][sp]);
                acc1[2][sp] = ffma2(wb2, hp1, acc1[2][sp]);
                acc1[3][sp] = ffma2(wb3, hp1, acc1[3][sp]);
            }
        }
#pragma unroll
        for (int i = 0; i < 4; i++)
#pragma unroll
            for (int sp = 0; sp < 4; sp++)
                unpack2(acc1[i][sp], hv[i][2 * sp], hv[i][2 * sp + 1]);
#pragma unroll
        for (int i = 0; i < 4; i++)
#pragma unroll
            for (int s = 0; s < 8; s++) hv[i][s] = fast_tanh(hv[i][s]);
        __syncwarp();
#pragma unroll
        for (int i = 0; i < 4; i++) {
            const int ro = hswz(u0 + i);
            *(float4*)(h1b + ro)      = make_float4(hv[i][0], hv[i][1], hv[i][2], hv[i][3]);
            *(float4*)(h1b + ro + 16) = make_float4(hv[i][4], hv[i][5], hv[i][6], hv[i][7]);
        }
        __syncwarp();
    }

    // ---- FC epilogue: out[b][c] = h1_final . fc_w[c] + fc_b[c]
    // 8 samples x 10 classes = 80 items per warp.
    for (int item = L; item < 8 * C_DIM; item += 32) {
        const int s = item / C_DIM;
        const int c = item % C_DIM;
        float acc = fc_b[c];
        const float* fw = fc_w + c * H_DIM;
#pragma unroll 8
        for (int k = 0; k < H_DIM; k++) {
            float hk = *(const float*)(h1b + hswz(k) + s * 4);
            acc = fmaf(hk, fw[k], acc);
        }
        out[(size_t)(sbase + s) * C_DIM + c] = acc;
    }
}

// ---------------- launch ----------------
extern "C" void kernel_launch(void* const* d_in, const int* in_sizes, int n_in,
                              void* d_out, int out_size) {
    (void)in_sizes; (void)n_in; (void)out_size;
    const float* x     = (const float*)d_in[0];
    const float* W_ih0 = (const float*)d_in[1];
    const float* W_hh0 = (const float*)d_in[2];
    const float* b_ih0 = (const float*)d_in[3];
    const float* b_hh0 = (const float*)d_in[4];
    const float* W_ih1 = (const float*)d_in[5];
    const float* W_hh1 = (const float*)d_in[6];
    const float* b_ih1 = (const float*)d_in[7];
    const float* b_hh1 = (const float*)d_in[8];
    const float* fc_w  = (const float*)d_in[9];
    const float* fc_b  = (const float*)d_in[10];
    float* out = (float*)d_out;

    xw0_kernel<<<B_TOTAL, 128>>>(x, W_ih0, b_ih0, b_hh0);

    cudaFuncSetAttribute(rnn_fused_kernel,
                         cudaFuncAttributeMaxDynamicSharedMemorySize, 229376);
    rnn_fused_kernel<<<B_TOTAL / 32, 128, 229376>>>(W_hh0, W_ih1, W_hh1, b_ih1,
                                                    b_hh1, fc_w, fc_b, out);
}